// round 4
// baseline (speedup 1.0000x reference)
#include <cuda_runtime.h>
#include <cstdint>
#include <cstddef>

#define DEV_INLINE __device__ __forceinline__

constexpr int D        = 512;      // feature dim
constexpr int FV       = 12;       // video frames
constexpr int VSTRIDE  = D + 4;    // padded shared row stride (floats), 16B-aligned rows
constexpr int THREADS  = 128;      // 4 warps
constexpr int RPW      = 5;        // text rows per warp (single pass)
constexpr int ROWS_CTA = 4 * RPW;  // 20 rows per CTA

// scratch (allocation-free: __device__ globals)
__device__ float g_part_min[8192];   // per-(sample,chunk) min cosine
__device__ float g_part_max[8192];   // per-(sample,chunk) max cosine
__device__ float g_rowval[1024];
__device__ float g_diagval[1024];

DEV_INLINE unsigned long long ffma2(unsigned long long a, unsigned long long b,
                                    unsigned long long c) {
    unsigned long long d;
    asm("fma.rn.f32x2 %0, %1, %2, %3;" : "=l"(d) : "l"(a), "l"(b), "l"(c));
    return d;
}

DEV_INLINE float hsum2(unsigned long long v) {
    float lo, hi;
    asm("mov.b64 {%0, %1}, %2;" : "=f"(lo), "=f"(hi) : "l"(v));
    return lo + hi;
}

// ---------------------------------------------------------------------------
// Kernel 1: per-(sample, chunk) min/max cosine over (20 text rows) x (12 video).
// grid = B * chunks, 128 threads. Warp layout: 4 f-groups x 8 d-lanes.
// Each f-group owns 3 video rows; each d-lane owns 64 interleaved floats
// (16B slice at (dl + 8*s)*16B). Each warp processes 5 text rows in a single
// pass. launch_bounds(128, 6): 85-reg budget -> 24 warps/SM (vs 16 at occ 4),
// trading per-warp prefetch depth for 1.5x more concurrent warps.
// ---------------------------------------------------------------------------
__global__ void __launch_bounds__(THREADS, 6)
sample_minmax_kernel(const float* __restrict__ text,
                     const float* __restrict__ video,
                     int T, int chunks)
{
    __shared__ float sv[FV * VSTRIDE];
    __shared__ float s_vinv[FV];
    __shared__ float s_wmin[4], s_wmax[4];

    const int b     = blockIdx.x / chunks;
    const int chunk = blockIdx.x % chunks;
    const int tid   = threadIdx.x;
    const int warp  = tid >> 5;
    const int lane  = tid & 31;
    const int fg    = lane >> 3;   // 0..3 : which group of 3 video rows
    const int dl    = lane & 7;    // 0..7 : which slice of D

    // ---- stage video tile [12 x 512] into padded shared (coalesced) ----
    const float4* vsrc = reinterpret_cast<const float4*>(video + (size_t)b * FV * D);
    for (int i = tid; i < FV * (D / 4); i += THREADS) {
        int f = i >> 7;            // / (D/4)
        int c = i & 127;
        *reinterpret_cast<float4*>(&sv[f * VSTRIDE + c * 4]) = vsrc[i];
    }
    __syncthreads();

    // ---- inverse norms of the 12 video rows (one warp per row, 3 rounds) ----
    for (int f = warp; f < FV; f += 4) {
        float s = 0.f;
        #pragma unroll
        for (int c = lane; c < D / 4; c += 32) {
            float4 x = *reinterpret_cast<const float4*>(&sv[f * VSTRIDE + c * 4]);
            s += x.x * x.x + x.y * x.y + x.z * x.z + x.w * x.w;
        }
        #pragma unroll
        for (int o = 16; o > 0; o >>= 1) s += __shfl_xor_sync(0xffffffffu, s, o);
        if (lane == 0) s_vinv[f] = rsqrtf(s);
    }
    __syncthreads();

    const int f0 = fg * 3;
    const float vinv0 = s_vinv[f0 + 0];
    const float vinv1 = s_vinv[f0 + 1];
    const float vinv2 = s_vinv[f0 + 2];
    const float* svp0 = &sv[(f0 + 0) * VSTRIDE];
    const float* svp1 = &sv[(f0 + 1) * VSTRIDE];
    const float* svp2 = &sv[(f0 + 2) * VSTRIDE];

    // ---- this warp's 5 text rows (clamped duplicates are harmless) ----
    const float* tb = text + (size_t)b * (size_t)T * D;
    const int base  = chunk * ROWS_CTA + warp * RPW;
    const float* trp[RPW];
    #pragma unroll
    for (int r = 0; r < RPW; r++) {
        int tt = base + r; if (tt > T - 1) tt = T - 1;
        trp[r] = tb + (size_t)tt * D;
    }

    unsigned long long acc[RPW][3];
    unsigned long long nrm[RPW];
    #pragma unroll
    for (int r = 0; r < RPW; r++) {
        acc[r][0] = 0ull; acc[r][1] = 0ull; acc[r][2] = 0ull; nrm[r] = 0ull;
    }

    #pragma unroll
    for (int s = 0; s < 16; s++) {
        const int off = (dl + 8 * s) * 4;                  // float offset, 16B aligned
        ulonglong2 v0 = *reinterpret_cast<const ulonglong2*>(svp0 + off);
        ulonglong2 v1 = *reinterpret_cast<const ulonglong2*>(svp1 + off);
        ulonglong2 v2 = *reinterpret_cast<const ulonglong2*>(svp2 + off);
        #pragma unroll
        for (int r = 0; r < RPW; r++) {
            ulonglong2 tv = *reinterpret_cast<const ulonglong2*>(trp[r] + off);
            acc[r][0] = ffma2(tv.x, v0.x, acc[r][0]);
            acc[r][0] = ffma2(tv.y, v0.y, acc[r][0]);
            acc[r][1] = ffma2(tv.x, v1.x, acc[r][1]);
            acc[r][1] = ffma2(tv.y, v1.y, acc[r][1]);
            acc[r][2] = ffma2(tv.x, v2.x, acc[r][2]);
            acc[r][2] = ffma2(tv.y, v2.y, acc[r][2]);
            nrm[r]    = ffma2(tv.x, tv.x, nrm[r]);
            nrm[r]    = ffma2(tv.y, tv.y, nrm[r]);
        }
    }

    // ---- reduction tail: once per warp, 5 independent row chains ----
    float wcmin = 1e30f, wcmax = -1e30f;
    #pragma unroll
    for (int r = 0; r < RPW; r++) {
        float d0 = hsum2(acc[r][0]);
        float d1 = hsum2(acc[r][1]);
        float d2 = hsum2(acc[r][2]);
        float ns = hsum2(nrm[r]);
        #pragma unroll
        for (int o = 1; o <= 4; o <<= 1) {                 // reduce across 8 d-lanes
            d0 += __shfl_xor_sync(0xffffffffu, d0, o);
            d1 += __shfl_xor_sync(0xffffffffu, d1, o);
            d2 += __shfl_xor_sync(0xffffffffu, d2, o);
            ns += __shfl_xor_sync(0xffffffffu, ns, o);
        }
        float rin = rsqrtf(ns);
        float c0 = d0 * rin * vinv0;
        float c1 = d1 * rin * vinv1;
        float c2 = d2 * rin * vinv2;
        float cmn = fminf(c0, fminf(c1, c2));
        float cmx = fmaxf(c0, fmaxf(c1, c2));
        // combine the 4 f-groups (lanes differing in bits 3,4)
        cmn = fminf(cmn, __shfl_xor_sync(0xffffffffu, cmn, 8));
        cmn = fminf(cmn, __shfl_xor_sync(0xffffffffu, cmn, 16));
        cmx = fmaxf(cmx, __shfl_xor_sync(0xffffffffu, cmx, 8));
        cmx = fmaxf(cmx, __shfl_xor_sync(0xffffffffu, cmx, 16));
        wcmin = fminf(wcmin, cmn);
        wcmax = fmaxf(wcmax, cmx);
    }

    if (lane == 0) { s_wmin[warp] = wcmin; s_wmax[warp] = wcmax; }
    __syncthreads();
    if (tid == 0) {
        float mn = fminf(fminf(s_wmin[0], s_wmin[1]), fminf(s_wmin[2], s_wmin[3]));
        float mx = fmaxf(fmaxf(s_wmax[0], s_wmax[1]), fmaxf(s_wmax[2], s_wmax[3]));
        g_part_min[blockIdx.x] = mn;   // min cos (chunk partial)
        g_part_max[blockIdx.x] = mx;   // max cos (chunk partial)
    }
}

// ---------------------------------------------------------------------------
// Kernel 2: combine chunk partials, global min/max, per-sample row/diag values.
// ---------------------------------------------------------------------------
__global__ void finalize_kernel(int B, int chunks)
{
    __shared__ float smx[256], smn[256];
    __shared__ float sh_mn, sh_inv;
    __shared__ float s_cmin[1024], s_cmax[1024];
    const int tid = threadIdx.x;

    float cmx = -1e30f, cmn = 1e30f;
    for (int i = tid; i < B; i += 256) {
        float m0 = 1e30f, m1 = -1e30f;
        for (int c = 0; c < chunks; c++) {
            m0 = fminf(m0, g_part_min[i * chunks + c]);
            m1 = fmaxf(m1, g_part_max[i * chunks + c]);
        }
        s_cmin[i] = m0;   // min cos for sample i  -> dmax_i = 1 - m0
        s_cmax[i] = m1;   // max cos for sample i  -> dmin_i = 1 - m1
        cmn = fminf(cmn, m0);
        cmx = fmaxf(cmx, m1);
    }
    smx[tid] = cmx; smn[tid] = cmn;
    __syncthreads();
    #pragma unroll
    for (int o = 128; o > 0; o >>= 1) {
        if (tid < o) {
            smx[tid] = fmaxf(smx[tid], smx[tid + o]);
            smn[tid] = fminf(smn[tid], smn[tid + o]);
        }
        __syncthreads();
    }
    if (tid == 0) {
        float mn = 1.0f - smx[0];        // min over all dis entries
        float mx = 1.0f - smn[0];        // max over all dis entries
        sh_mn  = mn;
        sh_inv = 1.0f / (mx - mn);
    }
    __syncthreads();
    const float mn  = sh_mn;
    const float inv = sh_inv;
    for (int i = tid; i < B; i += 256) {
        g_rowval[i]  = ((1.0f - s_cmin[i]) - mn) * inv;   // off-diagonal of row i
        g_diagval[i] = ((1.0f - s_cmax[i]) - mn) * inv;   // diagonal value
    }
}

// ---------------------------------------------------------------------------
// Kernel 3: fill the BxB output. One block per row, float4 stores.
// ---------------------------------------------------------------------------
__global__ void fill_kernel(float* __restrict__ out, int B)
{
    const int i  = blockIdx.x;
    const float rv = g_rowval[i];
    const float dv = g_diagval[i];
    float4* orow = reinterpret_cast<float4*>(out + (size_t)i * B);
    const int n4 = B >> 2;
    for (int c = threadIdx.x; c < n4; c += blockDim.x) {
        float4 v = make_float4(rv, rv, rv, rv);
        if (c == (i >> 2)) reinterpret_cast<float*>(&v)[i & 3] = dv;
        orow[c] = v;
    }
}

// ---------------------------------------------------------------------------
extern "C" void kernel_launch(void* const* d_in, const int* in_sizes, int n_in,
                              void* d_out, int out_size)
{
    const float* text  = (const float*)d_in[0];   // [B, T, D] fp32
    const float* video = (const float*)d_in[1];   // [B, F, D] fp32
    float* out = (float*)d_out;                   // [B, B] fp32

    const int B = in_sizes[1] / (FV * D);
    const int T = in_sizes[0] / (B * D);
    const int chunks = (T + ROWS_CTA - 1) / ROWS_CTA;   // 4 for T=77

    sample_minmax_kernel<<<B * chunks, THREADS>>>(text, video, T, chunks);
    finalize_kernel<<<1, 256>>>(B, chunks);
    fill_kernel<<<B, 128>>>(out, B);
}

// round 5
// speedup vs baseline: 1.8226x; 1.8226x over previous
#include <cuda_runtime.h>
#include <cstdint>
#include <cstddef>

#define DEV_INLINE __device__ __forceinline__

constexpr int D        = 512;       // feature dim
constexpr int FV       = 12;        // video frames
constexpr int VSTRIDE  = D + 4;     // video shared row stride (floats), 16B-aligned
constexpr int TSTRIDE  = D + 8;     // text shared row stride (floats), 16B-aligned
constexpr int THREADS  = 256;       // 8 warps
constexpr int RPW      = 5;         // text rows per warp (single pass)
constexpr int ROWS_CTA = 8 * RPW;   // 40 rows per CTA
constexpr int SMEM_FLOATS = FV * VSTRIDE + ROWS_CTA * TSTRIDE;
constexpr int SMEM_BYTES  = SMEM_FLOATS * 4;   // ~108 KB dynamic shared

// scratch (allocation-free: __device__ globals)
__device__ float g_part_min[4096];   // per-(sample,chunk) min cosine
__device__ float g_part_max[4096];   // per-(sample,chunk) max cosine
__device__ float g_rowval[1024];
__device__ float g_diagval[1024];

DEV_INLINE unsigned long long ffma2(unsigned long long a, unsigned long long b,
                                    unsigned long long c) {
    unsigned long long d;
    asm("fma.rn.f32x2 %0, %1, %2, %3;" : "=l"(d) : "l"(a), "l"(b), "l"(c));
    return d;
}

DEV_INLINE float hsum2(unsigned long long v) {
    float lo, hi;
    asm("mov.b64 {%0, %1}, %2;" : "=f"(lo), "=f"(hi) : "l"(v));
    return lo + hi;
}

DEV_INLINE void cp_async16(uint32_t smem_addr, const void* gptr) {
    asm volatile("cp.async.cg.shared.global [%0], [%1], 16;"
                 :: "r"(smem_addr), "l"(gptr));
}

// ---------------------------------------------------------------------------
// Kernel 1: per-(sample, chunk) min/max cosine over (40 text rows) x (12 video).
// grid = B*chunks, 256 threads (8 warps), occ 2 CTAs/SM.
// Prologue: ONE cp.async wave stages video tile (24KB) + full text tile (80KB)
// into shared -> the mainloop touches only LDS + FFMA2 (no DRAM latency in
// the loop). Warp layout: 4 f-groups x 8 d-lanes, RPW=5 rows per warp.
// ---------------------------------------------------------------------------
__global__ void __launch_bounds__(THREADS, 2)
sample_minmax_kernel(const float* __restrict__ text,
                     const float* __restrict__ video,
                     int T, int chunks)
{
    extern __shared__ float dsm[];
    float* sv = dsm;                          // [FV][VSTRIDE]
    float* st = dsm + FV * VSTRIDE;           // [ROWS_CTA][TSTRIDE]
    __shared__ float s_vinv[FV];
    __shared__ float s_wmin[8], s_wmax[8];

    const int b     = blockIdx.x / chunks;
    const int chunk = blockIdx.x % chunks;
    const int tid   = threadIdx.x;
    const int warp  = tid >> 5;
    const int lane  = tid & 31;
    const int fg    = lane >> 3;   // 0..3 : which group of 3 video rows
    const int dl    = lane & 7;    // 0..7 : which slice of D

    const char* vsrc = reinterpret_cast<const char*>(video + (size_t)b * FV * D);
    const char* tsrc = reinterpret_cast<const char*>(text  + (size_t)b * (size_t)T * D);
    const int base = chunk * ROWS_CTA;

    // ---- one cp.async wave: video (1536 x 16B) + text (5120 x 16B) ----
    {
        uint32_t svb = (uint32_t)__cvta_generic_to_shared(sv);
        uint32_t stb = (uint32_t)__cvta_generic_to_shared(st);
        constexpr int VCH = FV * 128;                 // video 16B-chunks
        constexpr int TCH = ROWS_CTA * 128;           // text  16B-chunks
        #pragma unroll 4
        for (int i = tid; i < VCH + TCH; i += THREADS) {
            if (i < VCH) {
                int f = i >> 7, c = i & 127;
                cp_async16(svb + (f * VSTRIDE + c * 4) * 4, vsrc + i * 16);
            } else {
                int j = i - VCH;
                int r = j >> 7, c = j & 127;
                int row = base + r; if (row > T - 1) row = T - 1;   // clamp dup
                cp_async16(stb + (r * TSTRIDE + c * 4) * 4,
                           tsrc + ((size_t)row * D + c * 4) * 4);
            }
        }
        asm volatile("cp.async.commit_group;");
        asm volatile("cp.async.wait_group 0;" ::: "memory");
    }
    __syncthreads();

    // ---- inverse norms of the 12 video rows (from shared) ----
    for (int f = warp; f < FV; f += 8) {
        float s = 0.f;
        #pragma unroll
        for (int c = lane; c < D / 4; c += 32) {
            float4 x = *reinterpret_cast<const float4*>(&sv[f * VSTRIDE + c * 4]);
            s += x.x * x.x + x.y * x.y + x.z * x.z + x.w * x.w;
        }
        #pragma unroll
        for (int o = 16; o > 0; o >>= 1) s += __shfl_xor_sync(0xffffffffu, s, o);
        if (lane == 0) s_vinv[f] = rsqrtf(s);
    }
    __syncthreads();

    const int f0 = fg * 3;
    const float vinv0 = s_vinv[f0 + 0];
    const float vinv1 = s_vinv[f0 + 1];
    const float vinv2 = s_vinv[f0 + 2];
    const float* svp0 = &sv[(f0 + 0) * VSTRIDE];
    const float* svp1 = &sv[(f0 + 1) * VSTRIDE];
    const float* svp2 = &sv[(f0 + 2) * VSTRIDE];

    // ---- this warp's 5 text rows, now resident in shared ----
    const float* trp[RPW];
    #pragma unroll
    for (int r = 0; r < RPW; r++)
        trp[r] = &st[(warp * RPW + r) * TSTRIDE];

    unsigned long long acc[RPW][3];
    unsigned long long nrm[RPW];
    #pragma unroll
    for (int r = 0; r < RPW; r++) {
        acc[r][0] = 0ull; acc[r][1] = 0ull; acc[r][2] = 0ull; nrm[r] = 0ull;
    }

    #pragma unroll
    for (int s = 0; s < 16; s++) {
        const int off = (dl + 8 * s) * 4;                  // float offset, 16B aligned
        ulonglong2 v0 = *reinterpret_cast<const ulonglong2*>(svp0 + off);
        ulonglong2 v1 = *reinterpret_cast<const ulonglong2*>(svp1 + off);
        ulonglong2 v2 = *reinterpret_cast<const ulonglong2*>(svp2 + off);
        #pragma unroll
        for (int r = 0; r < RPW; r++) {
            ulonglong2 tv = *reinterpret_cast<const ulonglong2*>(trp[r] + off);
            acc[r][0] = ffma2(tv.x, v0.x, acc[r][0]);
            acc[r][0] = ffma2(tv.y, v0.y, acc[r][0]);
            acc[r][1] = ffma2(tv.x, v1.x, acc[r][1]);
            acc[r][1] = ffma2(tv.y, v1.y, acc[r][1]);
            acc[r][2] = ffma2(tv.x, v2.x, acc[r][2]);
            acc[r][2] = ffma2(tv.y, v2.y, acc[r][2]);
            nrm[r]    = ffma2(tv.x, tv.x, nrm[r]);
            nrm[r]    = ffma2(tv.y, tv.y, nrm[r]);
        }
    }

    // ---- reduction tail: once per warp, 5 independent row chains ----
    float wcmin = 1e30f, wcmax = -1e30f;
    #pragma unroll
    for (int r = 0; r < RPW; r++) {
        float d0 = hsum2(acc[r][0]);
        float d1 = hsum2(acc[r][1]);
        float d2 = hsum2(acc[r][2]);
        float ns = hsum2(nrm[r]);
        #pragma unroll
        for (int o = 1; o <= 4; o <<= 1) {                 // reduce across 8 d-lanes
            d0 += __shfl_xor_sync(0xffffffffu, d0, o);
            d1 += __shfl_xor_sync(0xffffffffu, d1, o);
            d2 += __shfl_xor_sync(0xffffffffu, d2, o);
            ns += __shfl_xor_sync(0xffffffffu, ns, o);
        }
        float rin = rsqrtf(ns);
        float c0 = d0 * rin * vinv0;
        float c1 = d1 * rin * vinv1;
        float c2 = d2 * rin * vinv2;
        float cmn = fminf(c0, fminf(c1, c2));
        float cmx = fmaxf(c0, fmaxf(c1, c2));
        // combine the 4 f-groups (lanes differing in bits 3,4)
        cmn = fminf(cmn, __shfl_xor_sync(0xffffffffu, cmn, 8));
        cmn = fminf(cmn, __shfl_xor_sync(0xffffffffu, cmn, 16));
        cmx = fmaxf(cmx, __shfl_xor_sync(0xffffffffu, cmx, 8));
        cmx = fmaxf(cmx, __shfl_xor_sync(0xffffffffu, cmx, 16));
        wcmin = fminf(wcmin, cmn);
        wcmax = fmaxf(wcmax, cmx);
    }

    if (lane == 0) { s_wmin[warp] = wcmin; s_wmax[warp] = wcmax; }
    __syncthreads();
    if (tid == 0) {
        float mn = s_wmin[0], mx = s_wmax[0];
        #pragma unroll
        for (int w = 1; w < 8; w++) {
            mn = fminf(mn, s_wmin[w]);
            mx = fmaxf(mx, s_wmax[w]);
        }
        g_part_min[blockIdx.x] = mn;   // min cos (chunk partial)
        g_part_max[blockIdx.x] = mx;   // max cos (chunk partial)
    }
}

// ---------------------------------------------------------------------------
// Kernel 2: combine chunk partials, global min/max, per-sample row/diag values.
// ---------------------------------------------------------------------------
__global__ void finalize_kernel(int B, int chunks)
{
    __shared__ float smx[256], smn[256];
    __shared__ float sh_mn, sh_inv;
    __shared__ float s_cmin[1024], s_cmax[1024];
    const int tid = threadIdx.x;

    float cmx = -1e30f, cmn = 1e30f;
    for (int i = tid; i < B; i += 256) {
        float m0 = 1e30f, m1 = -1e30f;
        for (int c = 0; c < chunks; c++) {
            m0 = fminf(m0, g_part_min[i * chunks + c]);
            m1 = fmaxf(m1, g_part_max[i * chunks + c]);
        }
        s_cmin[i] = m0;   // min cos for sample i  -> dmax_i = 1 - m0
        s_cmax[i] = m1;   // max cos for sample i  -> dmin_i = 1 - m1
        cmn = fminf(cmn, m0);
        cmx = fmaxf(cmx, m1);
    }
    smx[tid] = cmx; smn[tid] = cmn;
    __syncthreads();
    #pragma unroll
    for (int o = 128; o > 0; o >>= 1) {
        if (tid < o) {
            smx[tid] = fmaxf(smx[tid], smx[tid + o]);
            smn[tid] = fminf(smn[tid], smn[tid + o]);
        }
        __syncthreads();
    }
    if (tid == 0) {
        float mn = 1.0f - smx[0];        // min over all dis entries
        float mx = 1.0f - smn[0];        // max over all dis entries
        sh_mn  = mn;
        sh_inv = 1.0f / (mx - mn);
    }
    __syncthreads();
    const float mn  = sh_mn;
    const float inv = sh_inv;
    for (int i = tid; i < B; i += 256) {
        g_rowval[i]  = ((1.0f - s_cmin[i]) - mn) * inv;   // off-diagonal of row i
        g_diagval[i] = ((1.0f - s_cmax[i]) - mn) * inv;   // diagonal value
    }
}

// ---------------------------------------------------------------------------
// Kernel 3: fill the BxB output. One block per row, float4 stores.
// ---------------------------------------------------------------------------
__global__ void fill_kernel(float* __restrict__ out, int B)
{
    const int i  = blockIdx.x;
    const float rv = g_rowval[i];
    const float dv = g_diagval[i];
    float4* orow = reinterpret_cast<float4*>(out + (size_t)i * B);
    const int n4 = B >> 2;
    for (int c = threadIdx.x; c < n4; c += blockDim.x) {
        float4 v = make_float4(rv, rv, rv, rv);
        if (c == (i >> 2)) reinterpret_cast<float*>(&v)[i & 3] = dv;
        orow[c] = v;
    }
}

// ---------------------------------------------------------------------------
extern "C" void kernel_launch(void* const* d_in, const int* in_sizes, int n_in,
                              void* d_out, int out_size)
{
    const float* text  = (const float*)d_in[0];   // [B, T, D] fp32
    const float* video = (const float*)d_in[1];   // [B, F, D] fp32
    float* out = (float*)d_out;                   // [B, B] fp32

    const int B = in_sizes[1] / (FV * D);
    const int T = in_sizes[0] / (B * D);
    const int chunks = (T + ROWS_CTA - 1) / ROWS_CTA;   // 2 for T=77

    cudaFuncSetAttribute(sample_minmax_kernel,
                         cudaFuncAttributeMaxDynamicSharedMemorySize, SMEM_BYTES);

    sample_minmax_kernel<<<B * chunks, THREADS, SMEM_BYTES>>>(text, video, T, chunks);
    finalize_kernel<<<1, 256>>>(B, chunks);
    fill_kernel<<<B, 128>>>(out, B);
}

// round 6
// speedup vs baseline: 1.9354x; 1.0619x over previous
#include <cuda_runtime.h>
#include <cstdint>
#include <cstddef>

#define DEV_INLINE __device__ __forceinline__

constexpr int D        = 512;       // feature dim
constexpr int FV       = 12;        // video frames
constexpr int THREADS  = 256;       // 8 warps
constexpr int RPW      = 5;         // text rows per warp (single pass)
constexpr int ROWS_CTA = 8 * RPW;   // 40 rows per CTA
constexpr int SMEM_FLOATS = (FV + ROWS_CTA) * D;    // no padding needed:
constexpr int SMEM_BYTES  = SMEM_FLOATS * 4;        // quarter-warp LDS phases are single-row

// scratch (allocation-free: __device__ globals)
__device__ float g_part_min[4096];
__device__ float g_part_max[4096];
__device__ float g_rowval[1024];
__device__ float g_diagval[1024];

DEV_INLINE unsigned long long ffma2(unsigned long long a, unsigned long long b,
                                    unsigned long long c) {
    unsigned long long d;
    asm("fma.rn.f32x2 %0, %1, %2, %3;" : "=l"(d) : "l"(a), "l"(b), "l"(c));
    return d;
}

DEV_INLINE float hsum2(unsigned long long v) {
    float lo, hi;
    asm("mov.b64 {%0, %1}, %2;" : "=f"(lo), "=f"(hi) : "l"(v));
    return lo + hi;
}

DEV_INLINE void cp_async16(uint32_t smem_addr, const void* gptr) {
    asm volatile("cp.async.cg.shared.global [%0], [%1], 16;"
                 :: "r"(smem_addr), "l"(gptr));
}
#define CP_COMMIT()  asm volatile("cp.async.commit_group;")
#define CP_WAIT(N)   asm volatile("cp.async.wait_group %0;" :: "n"(N) : "memory")

// ---------------------------------------------------------------------------
// Kernel 1: per-(sample, chunk) min/max cosine over (40 text rows) x (12 video).
// Pipelined staging: 4 cp.async commit groups split along D.
//   G0 = video (24KB) + text cols [0,128)   -> norms + mainloop steps 0..3
//   G1 = text cols [128,256)                -> steps 4..7
//   G2 = text cols [256,384)                -> steps 8..11
//   G3 = text cols [384,512)                -> steps 12..15
// DRAM transfer of later quarters overlaps compute on earlier ones.
// Warp layout: 4 f-groups x 8 d-lanes, RPW=5 rows per warp.
// ---------------------------------------------------------------------------
__global__ void __launch_bounds__(THREADS, 2)
sample_minmax_kernel(const float* __restrict__ text,
                     const float* __restrict__ video,
                     int T, int chunks)
{
    extern __shared__ float dsm[];
    float* sv = dsm;                          // [FV][D]
    float* st = dsm + FV * D;                 // [ROWS_CTA][D]
    __shared__ float s_vinv[FV];
    __shared__ float s_wmin[8], s_wmax[8];

    const int b     = blockIdx.x / chunks;
    const int chunk = blockIdx.x % chunks;
    const int tid   = threadIdx.x;
    const int warp  = tid >> 5;
    const int lane  = tid & 31;
    const int fg    = lane >> 3;   // 0..3 : which group of 3 video rows
    const int dl    = lane & 7;    // 0..7 : which slice of D

    const char* vsrc = reinterpret_cast<const char*>(video + (size_t)b * FV * D);
    const char* tsrc = reinterpret_cast<const char*>(text  + (size_t)b * (size_t)T * D);
    const int base = chunk * ROWS_CTA;

    // precompute clamped global row for this thread's staging lanes
    const uint32_t svb = (uint32_t)__cvta_generic_to_shared(sv);
    const uint32_t stb = (uint32_t)__cvta_generic_to_shared(st);

    // ---- G0: full video tile (contiguous) + text quarter 0 ----
    #pragma unroll
    for (int i = tid; i < FV * (D / 4); i += THREADS)        // 1536 chunks
        cp_async16(svb + i * 16, vsrc + i * 16);
    #pragma unroll
    for (int i = tid; i < ROWS_CTA * 32; i += THREADS) {     // 1280 chunks / quarter
        int r = i >> 5, c = i & 31;
        int row = base + r; if (row > T - 1) row = T - 1;    // clamp dup (harmless)
        cp_async16(stb + r * 2048 + c * 16, tsrc + (size_t)row * 2048 + c * 16);
    }
    CP_COMMIT();
    // ---- G1..G3: remaining text quarters ----
    #pragma unroll
    for (int q = 1; q < 4; q++) {
        #pragma unroll
        for (int i = tid; i < ROWS_CTA * 32; i += THREADS) {
            int r = i >> 5, c = i & 31;
            int row = base + r; if (row > T - 1) row = T - 1;
            cp_async16(stb + r * 2048 + q * 512 + c * 16,
                       tsrc + (size_t)row * 2048 + q * 512 + c * 16);
        }
        CP_COMMIT();
    }

    CP_WAIT(3);                    // G0 resident
    __syncthreads();

    // ---- inverse norms of the 12 video rows (from shared; overlaps G1..G3) ----
    for (int f = warp; f < FV; f += 8) {
        float s = 0.f;
        #pragma unroll
        for (int c = lane; c < D / 4; c += 32) {
            float4 x = *reinterpret_cast<const float4*>(&sv[f * D + c * 4]);
            s += x.x * x.x + x.y * x.y + x.z * x.z + x.w * x.w;
        }
        #pragma unroll
        for (int o = 16; o > 0; o >>= 1) s += __shfl_xor_sync(0xffffffffu, s, o);
        if (lane == 0) s_vinv[f] = rsqrtf(s);
    }
    __syncthreads();

    const int f0 = fg * 3;
    const float vinv0 = s_vinv[f0 + 0];
    const float vinv1 = s_vinv[f0 + 1];
    const float vinv2 = s_vinv[f0 + 2];
    const float* svp0 = &sv[(f0 + 0) * D];
    const float* svp1 = &sv[(f0 + 1) * D];
    const float* svp2 = &sv[(f0 + 2) * D];

    const float* trp[RPW];
    #pragma unroll
    for (int r = 0; r < RPW; r++)
        trp[r] = &st[(warp * RPW + r) * D];

    unsigned long long acc[RPW][3];
    unsigned long long nrm[RPW];
    #pragma unroll
    for (int r = 0; r < RPW; r++) {
        acc[r][0] = 0ull; acc[r][1] = 0ull; acc[r][2] = 0ull; nrm[r] = 0ull;
    }

    // ---- mainloop in 4 quarters, each gated on its cp.async group ----
    #pragma unroll
    for (int q = 0; q < 4; q++) {
        if (q == 1) { CP_WAIT(2); __syncthreads(); }
        if (q == 2) { CP_WAIT(1); __syncthreads(); }
        if (q == 3) { CP_WAIT(0); __syncthreads(); }
        #pragma unroll
        for (int si = 0; si < 4; si++) {
            const int s = q * 4 + si;
            const int off = (dl + 8 * s) * 4;              // float offset, 16B aligned
            ulonglong2 v0 = *reinterpret_cast<const ulonglong2*>(svp0 + off);
            ulonglong2 v1 = *reinterpret_cast<const ulonglong2*>(svp1 + off);
            ulonglong2 v2 = *reinterpret_cast<const ulonglong2*>(svp2 + off);
            #pragma unroll
            for (int r = 0; r < RPW; r++) {
                ulonglong2 tv = *reinterpret_cast<const ulonglong2*>(trp[r] + off);
                acc[r][0] = ffma2(tv.x, v0.x, acc[r][0]);
                acc[r][0] = ffma2(tv.y, v0.y, acc[r][0]);
                acc[r][1] = ffma2(tv.x, v1.x, acc[r][1]);
                acc[r][1] = ffma2(tv.y, v1.y, acc[r][1]);
                acc[r][2] = ffma2(tv.x, v2.x, acc[r][2]);
                acc[r][2] = ffma2(tv.y, v2.y, acc[r][2]);
                nrm[r]    = ffma2(tv.x, tv.x, nrm[r]);
                nrm[r]    = ffma2(tv.y, tv.y, nrm[r]);
            }
        }
    }

    // ---- reduction tail: once per warp, 5 independent row chains ----
    float wcmin = 1e30f, wcmax = -1e30f;
    #pragma unroll
    for (int r = 0; r < RPW; r++) {
        float d0 = hsum2(acc[r][0]);
        float d1 = hsum2(acc[r][1]);
        float d2 = hsum2(acc[r][2]);
        float ns = hsum2(nrm[r]);
        #pragma unroll
        for (int o = 1; o <= 4; o <<= 1) {                 // reduce across 8 d-lanes
            d0 += __shfl_xor_sync(0xffffffffu, d0, o);
            d1 += __shfl_xor_sync(0xffffffffu, d1, o);
            d2 += __shfl_xor_sync(0xffffffffu, d2, o);
            ns += __shfl_xor_sync(0xffffffffu, ns, o);
        }
        float rin = rsqrtf(ns);
        float c0 = d0 * rin * vinv0;
        float c1 = d1 * rin * vinv1;
        float c2 = d2 * rin * vinv2;
        float cmn = fminf(c0, fminf(c1, c2));
        float cmx = fmaxf(c0, fmaxf(c1, c2));
        cmn = fminf(cmn, __shfl_xor_sync(0xffffffffu, cmn, 8));
        cmn = fminf(cmn, __shfl_xor_sync(0xffffffffu, cmn, 16));
        cmx = fmaxf(cmx, __shfl_xor_sync(0xffffffffu, cmx, 8));
        cmx = fmaxf(cmx, __shfl_xor_sync(0xffffffffu, cmx, 16));
        wcmin = fminf(wcmin, cmn);
        wcmax = fmaxf(wcmax, cmx);
    }

    if (lane == 0) { s_wmin[warp] = wcmin; s_wmax[warp] = wcmax; }
    __syncthreads();
    if (tid == 0) {
        float mn = s_wmin[0], mx = s_wmax[0];
        #pragma unroll
        for (int w = 1; w < 8; w++) {
            mn = fminf(mn, s_wmin[w]);
            mx = fmaxf(mx, s_wmax[w]);
        }
        g_part_min[blockIdx.x] = mn;   // min cos (chunk partial)
        g_part_max[blockIdx.x] = mx;   // max cos (chunk partial)
    }
}

// ---------------------------------------------------------------------------
// Kernel 2: combine chunk partials, global min/max, per-sample row/diag values.
// ---------------------------------------------------------------------------
__global__ void finalize_kernel(int B, int chunks)
{
    __shared__ float smx[256], smn[256];
    __shared__ float sh_mn, sh_inv;
    __shared__ float s_cmin[1024], s_cmax[1024];
    const int tid = threadIdx.x;

    float cmx = -1e30f, cmn = 1e30f;
    for (int i = tid; i < B; i += 256) {
        float m0 = 1e30f, m1 = -1e30f;
        for (int c = 0; c < chunks; c++) {
            m0 = fminf(m0, g_part_min[i * chunks + c]);
            m1 = fmaxf(m1, g_part_max[i * chunks + c]);
        }
        s_cmin[i] = m0;
        s_cmax[i] = m1;
        cmn = fminf(cmn, m0);
        cmx = fmaxf(cmx, m1);
    }
    smx[tid] = cmx; smn[tid] = cmn;
    __syncthreads();
    #pragma unroll
    for (int o = 128; o > 0; o >>= 1) {
        if (tid < o) {
            smx[tid] = fmaxf(smx[tid], smx[tid + o]);
            smn[tid] = fminf(smn[tid], smn[tid + o]);
        }
        __syncthreads();
    }
    if (tid == 0) {
        float mn = 1.0f - smx[0];
        float mx = 1.0f - smn[0];
        sh_mn  = mn;
        sh_inv = 1.0f / (mx - mn);
    }
    __syncthreads();
    const float mn  = sh_mn;
    const float inv = sh_inv;
    for (int i = tid; i < B; i += 256) {
        g_rowval[i]  = ((1.0f - s_cmin[i]) - mn) * inv;
        g_diagval[i] = ((1.0f - s_cmax[i]) - mn) * inv;
    }
}

// ---------------------------------------------------------------------------
// Kernel 3: fill the BxB output. One block per row, float4 stores.
// ---------------------------------------------------------------------------
__global__ void fill_kernel(float* __restrict__ out, int B)
{
    const int i  = blockIdx.x;
    const float rv = g_rowval[i];
    const float dv = g_diagval[i];
    float4* orow = reinterpret_cast<float4*>(out + (size_t)i * B);
    const int n4 = B >> 2;
    for (int c = threadIdx.x; c < n4; c += blockDim.x) {
        float4 v = make_float4(rv, rv, rv, rv);
        if (c == (i >> 2)) reinterpret_cast<float*>(&v)[i & 3] = dv;
        orow[c] = v;
    }
}

// ---------------------------------------------------------------------------
extern "C" void kernel_launch(void* const* d_in, const int* in_sizes, int n_in,
                              void* d_out, int out_size)
{
    const float* text  = (const float*)d_in[0];   // [B, T, D] fp32
    const float* video = (const float*)d_in[1];   // [B, F, D] fp32
    float* out = (float*)d_out;                   // [B, B] fp32

    const int B = in_sizes[1] / (FV * D);
    const int T = in_sizes[0] / (B * D);
    const int chunks = (T + ROWS_CTA - 1) / ROWS_CTA;   // 2 for T=77

    cudaFuncSetAttribute(sample_minmax_kernel,
                         cudaFuncAttributeMaxDynamicSharedMemorySize, SMEM_BYTES);

    sample_minmax_kernel<<<B * chunks, THREADS, SMEM_BYTES>>>(text, video, T, chunks);
    finalize_kernel<<<1, 256>>>(B, chunks);
    fill_kernel<<<B, 128>>>(out, B);
}

// round 7
// speedup vs baseline: 2.0452x; 1.0567x over previous
#include <cuda_runtime.h>
#include <cstdint>
#include <cstddef>

#define DEV_INLINE __device__ __forceinline__

constexpr int D        = 512;       // feature dim
constexpr int FV       = 12;        // video frames
constexpr int THREADS  = 256;       // 8 warps
constexpr int RPW      = 5;         // text rows per warp (single pass)
constexpr int ROWS_CTA = 8 * RPW;   // 40 rows per CTA

// scratch (allocation-free: __device__ globals)
__device__ float g_part_min[4096];
__device__ float g_part_max[4096];

DEV_INLINE unsigned long long ffma2(unsigned long long a, unsigned long long b,
                                    unsigned long long c) {
    unsigned long long d;
    asm("fma.rn.f32x2 %0, %1, %2, %3;" : "=l"(d) : "l"(a), "l"(b), "l"(c));
    return d;
}

DEV_INLINE float hsum2(unsigned long long v) {
    float lo, hi;
    asm("mov.b64 {%0, %1}, %2;" : "=f"(lo), "=f"(hi) : "l"(v));
    return lo + hi;
}

DEV_INLINE void cp_async16(uint32_t smem_addr, const void* gptr) {
    asm volatile("cp.async.cg.shared.global [%0], [%1], 16;"
                 :: "r"(smem_addr), "l"(gptr));
}
#define CP_COMMIT()  asm volatile("cp.async.commit_group;")
#define CP_WAIT0()   asm volatile("cp.async.wait_group 0;" ::: "memory")

// ---------------------------------------------------------------------------
// Kernel 1: per-(sample, chunk) min/max cosine over (40 text rows) x (12 video).
// Video (24KB, reused by all 8 warps) staged in shared via one cp.async group.
// Text (single-use) is read DIRECTLY from global with LDG.128 + one-step
// register prefetch: each warp's lanes (8 distinct dl x 4 dup fgs) touch one
// 128B line per (row,step) -> 1 L1 wavefront, vs 4 LDS cycles when staged.
// Step-0 text LDGs are primed before the cp.async wait so the video-norm
// phase hides their DRAM latency.
// Warp layout: 4 f-groups x 8 d-lanes, RPW=5 rows per warp.
// ---------------------------------------------------------------------------
__global__ void __launch_bounds__(THREADS, 2)
sample_minmax_kernel(const float* __restrict__ text,
                     const float* __restrict__ video,
                     int T, int chunks)
{
    __shared__ float sv[FV * D];          // 24 KB video tile
    __shared__ float s_vinv[FV];
    __shared__ float s_wmin[8], s_wmax[8];

    const int b     = blockIdx.x / chunks;
    const int chunk = blockIdx.x % chunks;
    const int tid   = threadIdx.x;
    const int warp  = tid >> 5;
    const int lane  = tid & 31;
    const int fg    = lane >> 3;   // 0..3 : which group of 3 video rows
    const int dl    = lane & 7;    // 0..7 : which slice of D

    const char* vsrc = reinterpret_cast<const char*>(video + (size_t)b * FV * D);
    const float* tb  = text + (size_t)b * (size_t)T * D;
    const int base   = chunk * ROWS_CTA;

    // ---- issue video staging (one cp.async group) ----
    {
        uint32_t svb = (uint32_t)__cvta_generic_to_shared(sv);
        #pragma unroll
        for (int i = tid; i < FV * (D / 4); i += THREADS)
            cp_async16(svb + i * 16, vsrc + i * 16);
        CP_COMMIT();
    }

    // ---- text row pointers (clamped duplicates are harmless for min/max) ----
    const float* trp[RPW];
    #pragma unroll
    for (int r = 0; r < RPW; r++) {
        int tt = base + warp * RPW + r; if (tt > T - 1) tt = T - 1;
        trp[r] = tb + (size_t)tt * D;
    }

    // ---- prime step-0 text loads (independent of smem; hide behind norms) ----
    ulonglong2 tv[RPW];
    #pragma unroll
    for (int r = 0; r < RPW; r++)
        tv[r] = *reinterpret_cast<const ulonglong2*>(trp[r] + dl * 4);

    CP_WAIT0();
    __syncthreads();

    // ---- inverse norms of the 12 video rows (from shared) ----
    for (int f = warp; f < FV; f += 8) {
        float s = 0.f;
        #pragma unroll
        for (int c = lane; c < D / 4; c += 32) {
            float4 x = *reinterpret_cast<const float4*>(&sv[f * D + c * 4]);
            s += x.x * x.x + x.y * x.y + x.z * x.z + x.w * x.w;
        }
        #pragma unroll
        for (int o = 16; o > 0; o >>= 1) s += __shfl_xor_sync(0xffffffffu, s, o);
        if (lane == 0) s_vinv[f] = rsqrtf(s);
    }
    __syncthreads();

    const int f0 = fg * 3;
    const float vinv0 = s_vinv[f0 + 0];
    const float vinv1 = s_vinv[f0 + 1];
    const float vinv2 = s_vinv[f0 + 2];
    const float* svp0 = &sv[(f0 + 0) * D];
    const float* svp1 = &sv[(f0 + 1) * D];
    const float* svp2 = &sv[(f0 + 2) * D];

    unsigned long long acc[RPW][3];
    unsigned long long nrm[RPW];
    #pragma unroll
    for (int r = 0; r < RPW; r++) {
        acc[r][0] = 0ull; acc[r][1] = 0ull; acc[r][2] = 0ull; nrm[r] = 0ull;
    }

    // ---- mainloop: video from shared, text from global w/ 1-step prefetch ----
    #pragma unroll
    for (int s = 0; s < 16; s++) {
        const int off = (dl + 8 * s) * 4;                  // float offset, 16B aligned
        ulonglong2 tnx[RPW];
        if (s < 15) {
            const int noff = (dl + 8 * (s + 1)) * 4;
            #pragma unroll
            for (int r = 0; r < RPW; r++)
                tnx[r] = *reinterpret_cast<const ulonglong2*>(trp[r] + noff);
        }
        ulonglong2 v0 = *reinterpret_cast<const ulonglong2*>(svp0 + off);
        ulonglong2 v1 = *reinterpret_cast<const ulonglong2*>(svp1 + off);
        ulonglong2 v2 = *reinterpret_cast<const ulonglong2*>(svp2 + off);
        #pragma unroll
        for (int r = 0; r < RPW; r++) {
            acc[r][0] = ffma2(tv[r].x, v0.x, acc[r][0]);
            acc[r][0] = ffma2(tv[r].y, v0.y, acc[r][0]);
            acc[r][1] = ffma2(tv[r].x, v1.x, acc[r][1]);
            acc[r][1] = ffma2(tv[r].y, v1.y, acc[r][1]);
            acc[r][2] = ffma2(tv[r].x, v2.x, acc[r][2]);
            acc[r][2] = ffma2(tv[r].y, v2.y, acc[r][2]);
            nrm[r]    = ffma2(tv[r].x, tv[r].x, nrm[r]);
            nrm[r]    = ffma2(tv[r].y, tv[r].y, nrm[r]);
        }
        if (s < 15) {
            #pragma unroll
            for (int r = 0; r < RPW; r++) tv[r] = tnx[r];
        }
    }

    // ---- reduction tail: once per warp, 5 independent row chains ----
    float wcmin = 1e30f, wcmax = -1e30f;
    #pragma unroll
    for (int r = 0; r < RPW; r++) {
        float d0 = hsum2(acc[r][0]);
        float d1 = hsum2(acc[r][1]);
        float d2 = hsum2(acc[r][2]);
        float ns = hsum2(nrm[r]);
        #pragma unroll
        for (int o = 1; o <= 4; o <<= 1) {                 // reduce across 8 d-lanes
            d0 += __shfl_xor_sync(0xffffffffu, d0, o);
            d1 += __shfl_xor_sync(0xffffffffu, d1, o);
            d2 += __shfl_xor_sync(0xffffffffu, d2, o);
            ns += __shfl_xor_sync(0xffffffffu, ns, o);
        }
        float rin = rsqrtf(ns);
        float c0 = d0 * rin * vinv0;
        float c1 = d1 * rin * vinv1;
        float c2 = d2 * rin * vinv2;
        float cmn = fminf(c0, fminf(c1, c2));
        float cmx = fmaxf(c0, fmaxf(c1, c2));
        cmn = fminf(cmn, __shfl_xor_sync(0xffffffffu, cmn, 8));
        cmn = fminf(cmn, __shfl_xor_sync(0xffffffffu, cmn, 16));
        cmx = fmaxf(cmx, __shfl_xor_sync(0xffffffffu, cmx, 8));
        cmx = fmaxf(cmx, __shfl_xor_sync(0xffffffffu, cmx, 16));
        wcmin = fminf(wcmin, cmn);
        wcmax = fmaxf(wcmax, cmx);
    }

    if (lane == 0) { s_wmin[warp] = wcmin; s_wmax[warp] = wcmax; }
    __syncthreads();
    if (tid == 0) {
        float mn = s_wmin[0], mx = s_wmax[0];
        #pragma unroll
        for (int w = 1; w < 8; w++) {
            mn = fminf(mn, s_wmin[w]);
            mx = fmaxf(mx, s_wmax[w]);
        }
        g_part_min[blockIdx.x] = mn;   // min cos (chunk partial)
        g_part_max[blockIdx.x] = mx;   // max cos (chunk partial)
    }
}

// ---------------------------------------------------------------------------
// Kernel 2 (fused finalize + fill): one block per output row. Every block
// redundantly reduces the B*chunks partials (tiny, L2-resident) to the global
// min/max, derives its row/diag values, and writes its 2KB row.
// ---------------------------------------------------------------------------
__global__ void fill_finalize_kernel(float* __restrict__ out, int B, int chunks)
{
    __shared__ float smx[256], smn[256];
    __shared__ float sh_rv, sh_dv;
    const int i   = blockIdx.x;
    const int tid = threadIdx.x;
    const int n   = B * chunks;

    float cmx = -1e30f, cmn = 1e30f;
    for (int j = tid; j < n; j += 256) {
        cmn = fminf(cmn, g_part_min[j]);
        cmx = fmaxf(cmx, g_part_max[j]);
    }
    smx[tid] = cmx; smn[tid] = cmn;
    __syncthreads();
    #pragma unroll
    for (int o = 128; o > 0; o >>= 1) {
        if (tid < o) {
            smx[tid] = fmaxf(smx[tid], smx[tid + o]);
            smn[tid] = fminf(smn[tid], smn[tid + o]);
        }
        __syncthreads();
    }
    if (tid == 0) {
        const float mn  = 1.0f - smx[0];          // global min of dis
        const float mx  = 1.0f - smn[0];          // global max of dis
        const float inv = 1.0f / (mx - mn);
        float m0 = 1e30f, m1 = -1e30f;            // this row's chunk partials
        for (int c = 0; c < chunks; c++) {
            m0 = fminf(m0, g_part_min[i * chunks + c]);
            m1 = fmaxf(m1, g_part_max[i * chunks + c]);
        }
        sh_rv = ((1.0f - m0) - mn) * inv;         // off-diagonal (dmax_i)
        sh_dv = ((1.0f - m1) - mn) * inv;         // diagonal (dmin_i)
    }
    __syncthreads();

    const float rv = sh_rv;
    const float dv = sh_dv;
    float4* orow = reinterpret_cast<float4*>(out + (size_t)i * B);
    const int n4 = B >> 2;
    for (int c = tid; c < n4; c += 256) {
        float4 v = make_float4(rv, rv, rv, rv);
        if (c == (i >> 2)) reinterpret_cast<float*>(&v)[i & 3] = dv;
        orow[c] = v;
    }
}

// ---------------------------------------------------------------------------
extern "C" void kernel_launch(void* const* d_in, const int* in_sizes, int n_in,
                              void* d_out, int out_size)
{
    const float* text  = (const float*)d_in[0];   // [B, T, D] fp32
    const float* video = (const float*)d_in[1];   // [B, F, D] fp32
    float* out = (float*)d_out;                   // [B, B] fp32

    const int B = in_sizes[1] / (FV * D);
    const int T = in_sizes[0] / (B * D);
    const int chunks = (T + ROWS_CTA - 1) / ROWS_CTA;   // 2 for T=77

    sample_minmax_kernel<<<B * chunks, THREADS>>>(text, video, T, chunks);
    fill_finalize_kernel<<<B, 256>>>(out, B, chunks);
}